// round 7
// baseline (speedup 1.0000x reference)
#include <cuda_runtime.h>
#include <cuda_bf16.h>
#include <stdint.h>

#define B_ 2
#define N_ 512
#define IN_DIM 512
#define EMB 64
#define HID 128
#define NPOS 1025

// ---------------- device scratch (no cudaMalloc allowed) ----------------
__device__ float g_sl[B_ * N_ * EMB];
__device__ float g_sr[B_ * N_ * EMB];
__device__ float g_P[NPOS * HID];
__device__ unsigned short g_W1Th[HID * EMB];
__device__ unsigned short g_W1Tl[HID * EMB];
__device__ unsigned short g_W2Th[EMB * HID];
__device__ unsigned short g_W2Tl[EMB * HID];

// ---------------- helpers ----------------
__device__ __forceinline__ uint32_t smem_u32_of(const void* p) {
    uint32_t a;
    asm("{ .reg .u64 t; cvta.to.shared.u64 t, %1; cvt.u32.u64 %0, t; }"
        : "=r"(a) : "l"(p));
    return a;
}
__device__ __forceinline__ uint32_t pack_bf16(float e0, float e1) {
    __nv_bfloat162 t = __floats2bfloat162_rn(e0, e1);
    return *reinterpret_cast<uint32_t*>(&t);
}
__device__ __forceinline__ uint2 split2(float e0, float e1) {
    uint32_t hp = pack_bf16(e0, e1);
    float h0 = __uint_as_float(hp << 16);
    float h1 = __uint_as_float(hp & 0xFFFF0000u);
    uint32_t lp = pack_bf16(e0 - h0, e1 - h1);
    return make_uint2(hp, lp);
}
__device__ __forceinline__ void mma16816(float* c, const uint32_t* a,
                                         uint32_t b0, uint32_t b1) {
    asm volatile(
        "mma.sync.aligned.m16n8k16.row.col.f32.bf16.bf16.f32 "
        "{%0,%1,%2,%3}, {%4,%5,%6,%7}, {%8,%9}, {%0,%1,%2,%3};"
        : "+f"(c[0]), "+f"(c[1]), "+f"(c[2]), "+f"(c[3])
        : "r"(a[0]), "r"(a[1]), "r"(a[2]), "r"(a[3]), "r"(b0), "r"(b1));
}
__device__ __forceinline__ void ldsm4(uint32_t* r, uint32_t addr) {
    asm volatile("ldmatrix.sync.aligned.m8n8.x4.shared.b16 {%0,%1,%2,%3}, [%4];"
                 : "=r"(r[0]), "=r"(r[1]), "=r"(r[2]), "=r"(r[3]) : "r"(addr));
}

// ---------------- kernel 1: projections ----------------
__global__ void proj2_kernel(const float* __restrict__ s,
                             const float* __restrict__ Wl, const float* __restrict__ bl,
                             const float* __restrict__ Wr, const float* __restrict__ br) {
    extern __shared__ float psm[];
    float* SsT = psm;              // [512][20]
    float* Wc  = psm + 512 * 20;   // [64][128]

    const int t = threadIdx.x;
    const int r0 = blockIdx.x * 16;

    for (int i = t; i < 16 * IN_DIM; i += 256) {
        int row = i >> 9, k = i & 511;
        SsT[k * 20 + row] = s[(size_t)(r0 + row) * IN_DIM + k];
    }

    const int col = t & 127, rg = t >> 7;
    float acc[8];
    const float bias = (col < 64) ? bl[col] : br[col - 64];
#pragma unroll
    for (int r = 0; r < 8; r++) acc[r] = bias;
    __syncthreads();

    for (int kt = 0; kt < 8; kt++) {
        for (int i = t; i < 64 * 128; i += 256) {
            int k = i >> 7, c = i & 127;
            Wc[i] = (c < 64) ? Wl[(size_t)(kt * 64 + k) * 64 + c]
                             : Wr[(size_t)(kt * 64 + k) * 64 + (c - 64)];
        }
        __syncthreads();
#pragma unroll 4
        for (int k = 0; k < 64; k++) {
            float w = Wc[k * 128 + col];
            const float* sp = &SsT[(kt * 64 + k) * 20 + rg * 8];
            float4 a0 = *(const float4*)sp;
            float4 a1 = *(const float4*)(sp + 4);
            acc[0] += a0.x * w; acc[1] += a0.y * w; acc[2] += a0.z * w; acc[3] += a0.w * w;
            acc[4] += a1.x * w; acc[5] += a1.y * w; acc[6] += a1.z * w; acc[7] += a1.w * w;
        }
        __syncthreads();
    }
#pragma unroll
    for (int r = 0; r < 8; r++) {
        int row = r0 + rg * 8 + r;
        if (col < 64) g_sl[(size_t)row * 64 + col] = acc[r];
        else          g_sr[(size_t)row * 64 + (col - 64)] = acc[r];
    }
}

// ---------------- kernel 2: weight transposes + bf16 split ----------------
__global__ void prep_kernel(const float* __restrict__ W1, const float* __restrict__ W2) {
    int i = blockIdx.x * 256 + threadIdx.x;
    if (i < HID * EMB) {
        {
            int j = i >> 6, d = i & 63;
            float w = W1[d * HID + j];
            unsigned short hs = __bfloat16_as_ushort(__float2bfloat16(w));
            float hf = __uint_as_float((uint32_t)hs << 16);
            unsigned short ls = __bfloat16_as_ushort(__float2bfloat16(w - hf));
            g_W1Th[i] = hs; g_W1Tl[i] = ls;
        }
        {
            int o = i & 63, jj = i >> 6;
            float w = W2[jj * EMB + o];
            unsigned short hs = __bfloat16_as_ushort(__float2bfloat16(w));
            float hf = __uint_as_float((uint32_t)hs << 16);
            unsigned short ls = __bfloat16_as_ushort(__float2bfloat16(w - hf));
            g_W2Th[o * HID + jj] = hs; g_W2Tl[o * HID + jj] = ls;
        }
    }
}

// ---------------- kernel 3: positional table ----------------
__global__ void pos_kernel(const float* __restrict__ emb,
                           const float* __restrict__ W1,
                           const float* __restrict__ b1) {
    __shared__ float erow[EMB];
    const int dist = blockIdx.x;
    const int h = threadIdx.x;
    if (h < EMB) erow[h] = emb[dist * EMB + h];
    __syncthreads();
    float acc = b1[h];
#pragma unroll
    for (int d = 0; d < EMB; d++)
        acc = fmaf(erow[d], W1[(EMB + d) * HID + h], acc);
    g_P[dist * HID + h] = acc;
}

// ---------------- main kernel: 512 threads, 16 warps = 8 mg x 2 jh ----------------
// smem: W1 [128 j][72 bf16] stride 144B; W2 [64 o][136] stride 272B; A' [128 m][72] stride 144B
#define OFF_SL   0
#define OFF_W1H  256
#define OFF_W1L  (OFF_W1H + 18432)
#define OFF_W2H  (OFF_W1L + 18432)
#define OFF_W2L  (OFF_W2H + 17408)
#define OFF_AH   (OFF_W2L + 17408)
#define OFF_AL   (OFF_AH + 18432)
#define SMEM_MAIN (OFF_AL + 18432)   // 108800 bytes
#define OFF_SCR  OFF_AH              // 32KB partial-sum scratch (overlays A')

__global__ __launch_bounds__(512, 1)
void pair_mma_kernel(const float* __restrict__ b2, float* __restrict__ out) {
    extern __shared__ char sm[];
    const uint32_t smb = smem_u32_of(sm);
    const int tid = threadIdx.x;
    const int w = tid >> 5, l = tid & 31;
    const int mg = w >> 1;      // 8 m-groups of 16 rows
    const int jh = w & 1;       // 2 j-halves of 64
    const int n = blockIdx.x, b = blockIdx.y;

    float* sl = (float*)(sm + OFF_SL);
    if (tid < 64) sl[tid] = g_sl[((size_t)b * N_ + n) * EMB + tid];

    for (int i = tid; i < 2048; i += 512) {
        int j = i >> 4, d8 = (i & 15) * 8;
        *(uint2*)(sm + OFF_W1H + j * 144 + d8) = ((const uint2*)g_W1Th)[i];
        *(uint2*)(sm + OFF_W1L + j * 144 + d8) = ((const uint2*)g_W1Tl)[i];
    }
    for (int i = tid; i < 2048; i += 512) {
        int o = i >> 5, j8 = (i & 31) * 8;
        *(uint2*)(sm + OFF_W2H + o * 272 + j8) = ((const uint2*)g_W2Th)[i];
        *(uint2*)(sm + OFF_W2L + o * 272 + j8) = ((const uint2*)g_W2Tl)[i];
    }
    __syncthreads();

    // ---- per-thread ldmatrix base addresses (all x4 forms) ----
    // A: warp's 16 rows = [16*mg, 16*mg+16)
    const uint32_t preA = smb + OFF_AH + (16 * mg + (l & 15)) * 144 + (l >> 4) * 16;
    // B1 (W1): warp's j-half rows jh*64 + pattern; qq in 0..3 covers 64 j's
    const uint32_t preB1 = smb + OFF_W1H + jh * (64 * 144) +
        ((l & 7) + ((l >> 4) << 3)) * 144 + ((l >> 3) & 1) * 16;
    // B2 (W2): k-range = warp's j-half: byte offset jh*128 within each o-row
    const uint32_t preB2 = smb + OFF_W2H +
        ((l & 7) + ((l >> 4) << 3)) * 272 + ((l >> 3) & 1) * 16 + jh * 128;

    // per-thread output biases (this warp stores out cols [32*jh, 32*jh+32))
    float2 bias[4];
#pragma unroll
    for (int qi = 0; qi < 4; qi++)
        bias[qi] = __ldg((const float2*)(b2 + 8 * (4 * jh + qi) + (l & 3) * 2));

    for (int mt = 0; mt < 4; mt++) {
        const int m0 = mt * 128;

        // ---- build A'[m][d] = SR[m][d]*sl[d], hi/lo bf16 (512 threads) ----
        {
            const int row = tid >> 2, c0 = (tid & 3) * 16;
            const float4* s4 = (const float4*)(g_sr + ((size_t)(b * N_ + m0 + row)) * EMB + c0);
            const float4* sl4 = (const float4*)(sl + c0);
            char* dsth = sm + OFF_AH + row * 144 + c0 * 2;
            char* dstl = sm + OFF_AL + row * 144 + c0 * 2;
#pragma unroll
            for (int i = 0; i < 2; i++) {
                float4 v0 = s4[2 * i], v1 = s4[2 * i + 1];
                float4 w0 = sl4[2 * i], w1 = sl4[2 * i + 1];
                v0.x *= w0.x; v0.y *= w0.y; v0.z *= w0.z; v0.w *= w0.w;
                v1.x *= w1.x; v1.y *= w1.y; v1.z *= w1.z; v1.w *= w1.w;
                uint2 p0 = split2(v0.x, v0.y), p1 = split2(v0.z, v0.w);
                uint2 p2 = split2(v1.x, v1.y), p3 = split2(v1.z, v1.w);
                *(uint4*)(dsth + i * 16) = make_uint4(p0.x, p1.x, p2.x, p3.x);
                *(uint4*)(dstl + i * 16) = make_uint4(p0.y, p1.y, p2.y, p3.y);
            }
        }
        __syncthreads();

        // ---- GEMM1: warp tile 16m x 64j, K=64, 3-term hi/lo ----
        float D1[8][4];
#pragma unroll
        for (int q = 0; q < 8; q++)
#pragma unroll
            for (int e = 0; e < 4; e++) D1[q][e] = 0.0f;

#pragma unroll
        for (int t = 0; t < 4; t++) {
            uint32_t ah[4], al[4];
            ldsm4(ah, preA + t * 32);
            ldsm4(al, preA + 18432 + t * 32);
            uint32_t bhb[2][4], blb[2][4];
            ldsm4(bhb[0], preB1 + t * 32);
            ldsm4(blb[0], preB1 + 18432 + t * 32);
#pragma unroll
            for (int qq = 0; qq < 4; qq++) {
                const int cur = qq & 1, nxt = cur ^ 1;
                if (qq < 3) {
                    ldsm4(bhb[nxt], preB1 + (qq + 1) * 2304 + t * 32);
                    ldsm4(blb[nxt], preB1 + 18432 + (qq + 1) * 2304 + t * 32);
                }
                mma16816(D1[2 * qq],     ah, bhb[cur][0], bhb[cur][1]);
                mma16816(D1[2 * qq + 1], ah, bhb[cur][2], bhb[cur][3]);
                mma16816(D1[2 * qq],     ah, blb[cur][0], blb[cur][1]);
                mma16816(D1[2 * qq + 1], ah, blb[cur][2], blb[cur][3]);
                mma16816(D1[2 * qq],     al, bhb[cur][0], bhb[cur][1]);
                mma16816(D1[2 * qq + 1], al, bhb[cur][2], bhb[cur][3]);
            }
        }
        __syncthreads();   // A' consumed; scratch region now reusable

        // ---- relu(H + P[dist]) in registers (warp's j-half) ----
        const int m_t = m0 + 16 * mg + (l >> 2);
        {
            const float* P0 = g_P + (size_t)(n - m_t + 512) * HID + jh * 64;
            const float* P1 = P0 - 8 * HID;   // row m_t+8
#pragma unroll
            for (int q = 0; q < 8; q++) {
                const int jc = 8 * q + (l & 3) * 2;
                float2 p0 = __ldg((const float2*)(P0 + jc));
                float2 p1 = __ldg((const float2*)(P1 + jc));
                D1[q][0] = fmaxf(D1[q][0] + p0.x, 0.0f);
                D1[q][1] = fmaxf(D1[q][1] + p0.y, 0.0f);
                D1[q][2] = fmaxf(D1[q][2] + p1.x, 0.0f);
                D1[q][3] = fmaxf(D1[q][3] + p1.y, 0.0f);
            }
        }

        // ---- GEMM2: partial out = Hrelu(j-half) @ W2, K=64 ----
        float D2[8][4];
#pragma unroll
        for (int q = 0; q < 8; q++)
#pragma unroll
            for (int e = 0; e < 4; e++) D2[q][e] = 0.0f;

#pragma unroll
        for (int t2 = 0; t2 < 4; t2++) {
            uint32_t bhb[2][4], blb[2][4];
            ldsm4(bhb[0], preB2 + t2 * 32);
            ldsm4(blb[0], preB2 + 17408 + t2 * 32);

            uint32_t ah2[4], al2[4];
            {
                uint2 s0 = split2(D1[2 * t2][0],     D1[2 * t2][1]);
                uint2 s1 = split2(D1[2 * t2][2],     D1[2 * t2][3]);
                uint2 s2 = split2(D1[2 * t2 + 1][0], D1[2 * t2 + 1][1]);
                uint2 s3 = split2(D1[2 * t2 + 1][2], D1[2 * t2 + 1][3]);
                ah2[0] = s0.x; al2[0] = s0.y;
                ah2[1] = s1.x; al2[1] = s1.y;
                ah2[2] = s2.x; al2[2] = s2.y;
                ah2[3] = s3.x; al2[3] = s3.y;
            }
#pragma unroll
            for (int qq = 0; qq < 4; qq++) {
                const int cur = qq & 1, nxt = cur ^ 1;
                if (qq < 3) {
                    ldsm4(bhb[nxt], preB2 + (qq + 1) * 4352 + t2 * 32);
                    ldsm4(blb[nxt], preB2 + 17408 + (qq + 1) * 4352 + t2 * 32);
                }
                mma16816(D2[2 * qq],     ah2, bhb[cur][0], bhb[cur][1]);
                mma16816(D2[2 * qq + 1], ah2, bhb[cur][2], bhb[cur][3]);
                mma16816(D2[2 * qq],     ah2, blb[cur][0], blb[cur][1]);
                mma16816(D2[2 * qq + 1], ah2, blb[cur][2], blb[cur][3]);
                mma16816(D2[2 * qq],     al2, bhb[cur][0], bhb[cur][1]);
                mma16816(D2[2 * qq + 1], al2, bhb[cur][2], bhb[cur][3]);
            }
        }

        // ---- cross-warp K reduction: export the out-col half we don't store ----
        {
            char* exp_base = sm + OFF_SCR + (mg * 2 + jh) * 2048;
            const int qx = 4 * (1 - jh);   // partner's store half
#pragma unroll
            for (int qi = 0; qi < 4; qi++) {
                float* v = D2[qx + qi];
                *(float4*)(exp_base + qi * 512 + l * 16) =
                    make_float4(v[0], v[1], v[2], v[3]);
            }
        }
        __syncthreads();

        // ---- import partner's partials, add, + b2, store fp32 ----
        {
            const char* imp_base = sm + OFF_SCR + (mg * 2 + (1 - jh)) * 2048;
            const int q0 = 4 * jh;
            float* ob = out + (((size_t)b * N_ + n) * N_ + m_t) * EMB;
#pragma unroll
            for (int qi = 0; qi < 4; qi++) {
                float4 pv = *(const float4*)(imp_base + qi * 512 + l * 16);
                const int oc = 8 * (q0 + qi) + (l & 3) * 2;
                *(float2*)(ob + oc) =
                    make_float2(D2[q0 + qi][0] + pv.x + bias[qi].x,
                                D2[q0 + qi][1] + pv.y + bias[qi].y);
                *(float2*)(ob + 8 * EMB + oc) =
                    make_float2(D2[q0 + qi][2] + pv.z + bias[qi].x,
                                D2[q0 + qi][3] + pv.w + bias[qi].y);
            }
        }
        __syncthreads();   // scratch consumed before next A' build
    }
}

// ---------------- launch ----------------
extern "C" void kernel_launch(void* const* d_in, const int* in_sizes, int n_in,
                              void* d_out, int out_size) {
    const float* s       = (const float*)d_in[0];
    const float* W_left  = (const float*)d_in[1];
    const float* b_left  = (const float*)d_in[2];
    const float* W_right = (const float*)d_in[3];
    const float* b_right = (const float*)d_in[4];
    const float* emb     = (const float*)d_in[5];
    const float* W1      = (const float*)d_in[6];
    const float* b1      = (const float*)d_in[7];
    const float* W2      = (const float*)d_in[8];
    const float* b2      = (const float*)d_in[9];
    float* out = (float*)d_out;

    cudaFuncSetAttribute(proj2_kernel,
                         cudaFuncAttributeMaxDynamicSharedMemorySize, 73728);
    cudaFuncSetAttribute(pair_mma_kernel,
                         cudaFuncAttributeMaxDynamicSharedMemorySize, SMEM_MAIN);

    proj2_kernel<<<64, 256, 73728>>>(s, W_left, b_left, W_right, b_right);
    prep_kernel<<<32, 256>>>(W1, W2);
    pos_kernel<<<NPOS, 128>>>(emb, W1, b1);
    pair_mma_kernel<<<dim3(N_, B_), 512, SMEM_MAIN>>>(b2, out);
}

// round 8
// speedup vs baseline: 1.2410x; 1.2410x over previous
#include <cuda_runtime.h>
#include <cuda_fp16.h>
#include <stdint.h>

#define B_ 2
#define N_ 512
#define IN_DIM 512
#define EMB 64
#define HID 128
#define NPOS 1025

// ---------------- device scratch (no cudaMalloc allowed) ----------------
__device__ float g_sl[B_ * N_ * EMB];
__device__ float g_sr[B_ * N_ * EMB];
__device__ float g_P[NPOS * HID];
__device__ unsigned short g_W1Th[HID * EMB];   // fp16(W1_top^T) [j][d]
__device__ unsigned short g_W2Th[EMB * HID];   // fp16(W2^T) [o][j]

// ---------------- helpers ----------------
__device__ __forceinline__ uint32_t smem_u32_of(const void* p) {
    uint32_t a;
    asm("{ .reg .u64 t; cvta.to.shared.u64 t, %1; cvt.u32.u64 %0, t; }"
        : "=r"(a) : "l"(p));
    return a;
}
// fp16 hi/lo split of a float pair -> (hi_half2, lo_half2)
__device__ __forceinline__ uint2 split2h(float e0, float e1) {
    __half2 h = __floats2half2_rn(e0, e1);
    float f0 = __half2float(__low2half(h));
    float f1 = __half2float(__high2half(h));
    __half2 lo = __floats2half2_rn(e0 - f0, e1 - f1);
    return make_uint2(*reinterpret_cast<uint32_t*>(&h),
                      *reinterpret_cast<uint32_t*>(&lo));
}
__device__ __forceinline__ void mma16816(float* c, const uint32_t* a,
                                         uint32_t b0, uint32_t b1) {
    asm volatile(
        "mma.sync.aligned.m16n8k16.row.col.f32.f16.f16.f32 "
        "{%0,%1,%2,%3}, {%4,%5,%6,%7}, {%8,%9}, {%0,%1,%2,%3};"
        : "+f"(c[0]), "+f"(c[1]), "+f"(c[2]), "+f"(c[3])
        : "r"(a[0]), "r"(a[1]), "r"(a[2]), "r"(a[3]), "r"(b0), "r"(b1));
}
__device__ __forceinline__ void ldsm4(uint32_t* r, uint32_t addr) {
    asm volatile("ldmatrix.sync.aligned.m8n8.x4.shared.b16 {%0,%1,%2,%3}, [%4];"
                 : "=r"(r[0]), "=r"(r[1]), "=r"(r[2]), "=r"(r[3]) : "r"(addr));
}

// ---------------- kernel 1: projections ----------------
__global__ void proj2_kernel(const float* __restrict__ s,
                             const float* __restrict__ Wl, const float* __restrict__ bl,
                             const float* __restrict__ Wr, const float* __restrict__ br) {
    extern __shared__ float psm[];
    float* SsT = psm;              // [512][20]
    float* Wc  = psm + 512 * 20;   // [64][128]

    const int t = threadIdx.x;
    const int r0 = blockIdx.x * 16;

    for (int i = t; i < 16 * IN_DIM; i += 256) {
        int row = i >> 9, k = i & 511;
        SsT[k * 20 + row] = s[(size_t)(r0 + row) * IN_DIM + k];
    }

    const int col = t & 127, rg = t >> 7;
    float acc[8];
    const float bias = (col < 64) ? bl[col] : br[col - 64];
#pragma unroll
    for (int r = 0; r < 8; r++) acc[r] = bias;
    __syncthreads();

    for (int kt = 0; kt < 8; kt++) {
        for (int i = t; i < 64 * 128; i += 256) {
            int k = i >> 7, c = i & 127;
            Wc[i] = (c < 64) ? Wl[(size_t)(kt * 64 + k) * 64 + c]
                             : Wr[(size_t)(kt * 64 + k) * 64 + (c - 64)];
        }
        __syncthreads();
#pragma unroll 4
        for (int k = 0; k < 64; k++) {
            float w = Wc[k * 128 + col];
            const float* sp = &SsT[(kt * 64 + k) * 20 + rg * 8];
            float4 a0 = *(const float4*)sp;
            float4 a1 = *(const float4*)(sp + 4);
            acc[0] += a0.x * w; acc[1] += a0.y * w; acc[2] += a0.z * w; acc[3] += a0.w * w;
            acc[4] += a1.x * w; acc[5] += a1.y * w; acc[6] += a1.z * w; acc[7] += a1.w * w;
        }
        __syncthreads();
    }
#pragma unroll
    for (int r = 0; r < 8; r++) {
        int row = r0 + rg * 8 + r;
        if (col < 64) g_sl[(size_t)row * 64 + col] = acc[r];
        else          g_sr[(size_t)row * 64 + (col - 64)] = acc[r];
    }
}

// ---------------- kernel 2: weight transposes -> fp16 ----------------
__global__ void prep_kernel(const float* __restrict__ W1, const float* __restrict__ W2) {
    int i = blockIdx.x * 256 + threadIdx.x;
    if (i < HID * EMB) {
        {
            int j = i >> 6, d = i & 63;
            __half h = __float2half_rn(W1[d * HID + j]);
            g_W1Th[i] = __half_as_ushort(h);
        }
        {
            int o = i & 63, jj = i >> 6;
            __half h = __float2half_rn(W2[jj * EMB + o]);
            g_W2Th[o * HID + jj] = __half_as_ushort(h);
        }
    }
}

// ---------------- kernel 3: positional table ----------------
__global__ void pos_kernel(const float* __restrict__ emb,
                           const float* __restrict__ W1,
                           const float* __restrict__ b1) {
    __shared__ float erow[EMB];
    const int dist = blockIdx.x;
    const int h = threadIdx.x;
    if (h < EMB) erow[h] = emb[dist * EMB + h];
    __syncthreads();
    float acc = b1[h];
#pragma unroll
    for (int d = 0; d < EMB; d++)
        acc = fmaf(erow[d], W1[(EMB + d) * HID + h], acc);
    g_P[dist * HID + h] = acc;
}

// ---------------- main kernel: fp16 2-term (A hi/lo split, B single) ----------------
// smem: W1 [128 j][72 fp16] stride 144B; W2 [64 o][136] stride 272B;
//       A' hi/lo [128 m][72] stride 144B each
#define OFF_SL   0
#define OFF_W1   256
#define OFF_W2   (OFF_W1 + 18432)
#define OFF_AH   (OFF_W2 + 17408)
#define OFF_AL   (OFF_AH + 18432)
#define SMEM_MAIN (OFF_AL + 18432)   // 72960 bytes

__global__ __launch_bounds__(256, 1)
void pair_mma_kernel(const float* __restrict__ b2, float* __restrict__ out) {
    extern __shared__ char sm[];
    const uint32_t smb = smem_u32_of(sm);
    const int tid = threadIdx.x;
    const int w = tid >> 5, l = tid & 31;
    const int n = blockIdx.x, b = blockIdx.y;

    float* sl = (float*)(sm + OFF_SL);
    if (tid < 64) sl[tid] = g_sl[((size_t)b * N_ + n) * EMB + tid];

    for (int i = tid; i < 2048; i += 256) {
        int j = i >> 4, d8 = (i & 15) * 8;
        *(uint2*)(sm + OFF_W1 + j * 144 + d8) = ((const uint2*)g_W1Th)[i];
    }
    for (int i = tid; i < 2048; i += 256) {
        int o = i >> 5, j8 = (i & 31) * 8;
        *(uint2*)(sm + OFF_W2 + o * 272 + j8) = ((const uint2*)g_W2Th)[i];
    }

    // ---- per-thread ldmatrix base addresses (all x4 forms) ----
    const uint32_t preA = smb + OFF_AH + (16 * w + (l & 15)) * 144 + (l >> 4) * 16;
    const uint32_t preB1 = smb + OFF_W1 +
        ((l & 7) + ((l >> 4) << 3)) * 144 + ((l >> 3) & 1) * 16;
    const uint32_t preB2 = smb + OFF_W2 +
        ((l & 7) + ((l >> 4) << 3)) * 272 + ((l >> 3) & 1) * 16;

    float2 bias[8];
#pragma unroll
    for (int q = 0; q < 8; q++)
        bias[q] = __ldg((const float2*)(b2 + 8 * q + (l & 3) * 2));

    // ---- prefetch first SR slice into registers ----
    const int arow = tid >> 1, ac0 = (tid & 1) * 32;
    float4 srg[8];
    {
        const float4* s4 = (const float4*)(g_sr + ((size_t)(b * N_ + arow)) * EMB + ac0);
#pragma unroll
        for (int i = 0; i < 8; i++) srg[i] = s4[i];
    }
    __syncthreads();

    for (int mt = 0; mt < 4; mt++) {
        // ---- build A'[m][d] = SR[m][d]*sl[d], fp16 hi/lo (from prefetched regs) ----
        {
            const float4* sl4 = (const float4*)(sl + ac0);
            char* dsth = sm + OFF_AH + arow * 144 + ac0 * 2;
            char* dstl = sm + OFF_AL + arow * 144 + ac0 * 2;
#pragma unroll
            for (int i = 0; i < 4; i++) {
                float4 v0 = srg[2 * i], v1 = srg[2 * i + 1];
                float4 w0 = sl4[2 * i], w1 = sl4[2 * i + 1];
                v0.x *= w0.x; v0.y *= w0.y; v0.z *= w0.z; v0.w *= w0.w;
                v1.x *= w1.x; v1.y *= w1.y; v1.z *= w1.z; v1.w *= w1.w;
                uint2 p0 = split2h(v0.x, v0.y), p1 = split2h(v0.z, v0.w);
                uint2 p2 = split2h(v1.x, v1.y), p3 = split2h(v1.z, v1.w);
                *(uint4*)(dsth + i * 16) = make_uint4(p0.x, p1.x, p2.x, p3.x);
                *(uint4*)(dstl + i * 16) = make_uint4(p0.y, p1.y, p2.y, p3.y);
            }
        }
        __syncthreads();

        // ---- prefetch next mt's SR slice (LDG hidden under GEMMs) ----
        if (mt < 3) {
            const float4* s4 = (const float4*)(g_sr +
                ((size_t)(b * N_ + (mt + 1) * 128 + arow)) * EMB + ac0);
#pragma unroll
            for (int i = 0; i < 8; i++) srg[i] = s4[i];
        }

        // ---- GEMM1: H[128,128] = A' @ W1^T, 2-term fp16 ----
        float D1[16][4];
#pragma unroll
        for (int q = 0; q < 16; q++)
#pragma unroll
            for (int e = 0; e < 4; e++) D1[q][e] = 0.0f;

#pragma unroll
        for (int t = 0; t < 4; t++) {
            uint32_t ah[4], al[4];
            ldsm4(ah, preA + t * 32);
            ldsm4(al, preA + 18432 + t * 32);
            uint32_t bhb[2][4];
            ldsm4(bhb[0], preB1 + t * 32);
#pragma unroll
            for (int qq = 0; qq < 8; qq++) {
                const int cur = qq & 1, nxt = cur ^ 1;
                if (qq < 7)
                    ldsm4(bhb[nxt], preB1 + (qq + 1) * 2304 + t * 32);
                mma16816(D1[2 * qq],     ah, bhb[cur][0], bhb[cur][1]);
                mma16816(D1[2 * qq + 1], ah, bhb[cur][2], bhb[cur][3]);
                mma16816(D1[2 * qq],     al, bhb[cur][0], bhb[cur][1]);
                mma16816(D1[2 * qq + 1], al, bhb[cur][2], bhb[cur][3]);
            }
        }
        __syncthreads();   // A' consumed; next tile may rebuild

        // ---- relu(H + P[dist]) in registers ----
        const int m_t = mt * 128 + 16 * w + (l >> 2);
        {
            const float* P0 = g_P + (size_t)(n - m_t + 512) * HID;
            const float* P1 = P0 - 8 * HID;   // row m_t+8
#pragma unroll
            for (int q = 0; q < 16; q++) {
                const int jc = 8 * q + (l & 3) * 2;
                float2 p0 = __ldg((const float2*)(P0 + jc));
                float2 p1 = __ldg((const float2*)(P1 + jc));
                D1[q][0] = fmaxf(D1[q][0] + p0.x, 0.0f);
                D1[q][1] = fmaxf(D1[q][1] + p0.y, 0.0f);
                D1[q][2] = fmaxf(D1[q][2] + p1.x, 0.0f);
                D1[q][3] = fmaxf(D1[q][3] + p1.y, 0.0f);
            }
        }

        // ---- GEMM2: out = Hrelu @ W2, 2-term fp16 (A from registers) ----
        float D2[8][4];
#pragma unroll
        for (int q = 0; q < 8; q++)
#pragma unroll
            for (int e = 0; e < 4; e++) D2[q][e] = 0.0f;

#pragma unroll
        for (int t2 = 0; t2 < 8; t2++) {
            uint32_t bhb[2][4];
            ldsm4(bhb[0], preB2 + t2 * 32);

            uint32_t ah2[4], al2[4];
            {
                uint2 s0 = split2h(D1[2 * t2][0],     D1[2 * t2][1]);
                uint2 s1 = split2h(D1[2 * t2][2],     D1[2 * t2][3]);
                uint2 s2 = split2h(D1[2 * t2 + 1][0], D1[2 * t2 + 1][1]);
                uint2 s3 = split2h(D1[2 * t2 + 1][2], D1[2 * t2 + 1][3]);
                ah2[0] = s0.x; al2[0] = s0.y;
                ah2[1] = s1.x; al2[1] = s1.y;
                ah2[2] = s2.x; al2[2] = s2.y;
                ah2[3] = s3.x; al2[3] = s3.y;
            }
#pragma unroll
            for (int qq = 0; qq < 4; qq++) {
                const int cur = qq & 1, nxt = cur ^ 1;
                if (qq < 3)
                    ldsm4(bhb[nxt], preB2 + (qq + 1) * 4352 + t2 * 32);
                mma16816(D2[2 * qq],     ah2, bhb[cur][0], bhb[cur][1]);
                mma16816(D2[2 * qq + 1], ah2, bhb[cur][2], bhb[cur][3]);
                mma16816(D2[2 * qq],     al2, bhb[cur][0], bhb[cur][1]);
                mma16816(D2[2 * qq + 1], al2, bhb[cur][2], bhb[cur][3]);
            }
        }

        // ---- epilogue: + b2, store fp32 ----
        {
            float* ob = out + (((size_t)b * N_ + n) * N_ + m_t) * EMB;
#pragma unroll
            for (int q = 0; q < 8; q++) {
                const int oc = 8 * q + (l & 3) * 2;
                *(float2*)(ob + oc) =
                    make_float2(D2[q][0] + bias[q].x, D2[q][1] + bias[q].y);
                *(float2*)(ob + 8 * EMB + oc) =
                    make_float2(D2[q][2] + bias[q].x, D2[q][3] + bias[q].y);
            }
        }
    }
}

// ---------------- launch ----------------
extern "C" void kernel_launch(void* const* d_in, const int* in_sizes, int n_in,
                              void* d_out, int out_size) {
    const float* s       = (const float*)d_in[0];
    const float* W_left  = (const float*)d_in[1];
    const float* b_left  = (const float*)d_in[2];
    const float* W_right = (const float*)d_in[3];
    const float* b_right = (const float*)d_in[4];
    const float* emb     = (const float*)d_in[5];
    const float* W1      = (const float*)d_in[6];
    const float* b1      = (const float*)d_in[7];
    const float* W2      = (const float*)d_in[8];
    const float* b2      = (const float*)d_in[9];
    float* out = (float*)d_out;

    cudaFuncSetAttribute(proj2_kernel,
                         cudaFuncAttributeMaxDynamicSharedMemorySize, 73728);
    cudaFuncSetAttribute(pair_mma_kernel,
                         cudaFuncAttributeMaxDynamicSharedMemorySize, SMEM_MAIN);

    proj2_kernel<<<64, 256, 73728>>>(s, W_left, b_left, W_right, b_right);
    prep_kernel<<<32, 256>>>(W1, W2);
    pos_kernel<<<NPOS, 128>>>(emb, W1, b1);
    pair_mma_kernel<<<dim3(N_, B_), 256, SMEM_MAIN>>>(b2, out);
}

// round 9
// speedup vs baseline: 1.3150x; 1.0596x over previous
#include <cuda_runtime.h>
#include <cuda_fp16.h>
#include <stdint.h>

#define B_ 2
#define N_ 512
#define IN_DIM 512
#define EMB 64
#define HID 128
#define NPOS 1025

// ---------------- device scratch (no cudaMalloc allowed) ----------------
__device__ float g_sl[B_ * N_ * EMB];
__device__ float g_sr[B_ * N_ * EMB];
__device__ float g_P[NPOS * HID];
__device__ unsigned short g_W1Th[HID * EMB];   // fp16(W1_top^T) [j][d]
__device__ unsigned short g_W2Th[EMB * HID];   // fp16(W2^T) [o][j]

// ---------------- helpers ----------------
__device__ __forceinline__ uint32_t smem_u32_of(const void* p) {
    uint32_t a;
    asm("{ .reg .u64 t; cvta.to.shared.u64 t, %1; cvt.u32.u64 %0, t; }"
        : "=r"(a) : "l"(p));
    return a;
}
// fp16 hi/lo split of a float pair -> (hi_half2, lo_half2)
__device__ __forceinline__ uint2 split2h(float e0, float e1) {
    __half2 h = __floats2half2_rn(e0, e1);
    float f0 = __half2float(__low2half(h));
    float f1 = __half2float(__high2half(h));
    __half2 lo = __floats2half2_rn(e0 - f0, e1 - f1);
    return make_uint2(*reinterpret_cast<uint32_t*>(&h),
                      *reinterpret_cast<uint32_t*>(&lo));
}
__device__ __forceinline__ void mma16816(float* c, const uint32_t* a,
                                         uint32_t b0, uint32_t b1) {
    asm volatile(
        "mma.sync.aligned.m16n8k16.row.col.f32.f16.f16.f32 "
        "{%0,%1,%2,%3}, {%4,%5,%6,%7}, {%8,%9}, {%0,%1,%2,%3};"
        : "+f"(c[0]), "+f"(c[1]), "+f"(c[2]), "+f"(c[3])
        : "r"(a[0]), "r"(a[1]), "r"(a[2]), "r"(a[3]), "r"(b0), "r"(b1));
}
__device__ __forceinline__ void ldsm4(uint32_t* r, uint32_t addr) {
    asm volatile("ldmatrix.sync.aligned.m8n8.x4.shared.b16 {%0,%1,%2,%3}, [%4];"
                 : "=r"(r[0]), "=r"(r[1]), "=r"(r[2]), "=r"(r[3]) : "r"(addr));
}

// ---------------- kernel 1: projections ----------------
__global__ void proj2_kernel(const float* __restrict__ s,
                             const float* __restrict__ Wl, const float* __restrict__ bl,
                             const float* __restrict__ Wr, const float* __restrict__ br) {
    extern __shared__ float psm[];
    float* SsT = psm;              // [512][20]
    float* Wc  = psm + 512 * 20;   // [64][128]

    const int t = threadIdx.x;
    const int r0 = blockIdx.x * 16;

    for (int i = t; i < 16 * IN_DIM; i += 256) {
        int row = i >> 9, k = i & 511;
        SsT[k * 20 + row] = s[(size_t)(r0 + row) * IN_DIM + k];
    }

    const int col = t & 127, rg = t >> 7;
    float acc[8];
    const float bias = (col < 64) ? bl[col] : br[col - 64];
#pragma unroll
    for (int r = 0; r < 8; r++) acc[r] = bias;
    __syncthreads();

    for (int kt = 0; kt < 8; kt++) {
        for (int i = t; i < 64 * 128; i += 256) {
            int k = i >> 7, c = i & 127;
            Wc[i] = (c < 64) ? Wl[(size_t)(kt * 64 + k) * 64 + c]
                             : Wr[(size_t)(kt * 64 + k) * 64 + (c - 64)];
        }
        __syncthreads();
#pragma unroll 4
        for (int k = 0; k < 64; k++) {
            float w = Wc[k * 128 + col];
            const float* sp = &SsT[(kt * 64 + k) * 20 + rg * 8];
            float4 a0 = *(const float4*)sp;
            float4 a1 = *(const float4*)(sp + 4);
            acc[0] += a0.x * w; acc[1] += a0.y * w; acc[2] += a0.z * w; acc[3] += a0.w * w;
            acc[4] += a1.x * w; acc[5] += a1.y * w; acc[6] += a1.z * w; acc[7] += a1.w * w;
        }
        __syncthreads();
    }
#pragma unroll
    for (int r = 0; r < 8; r++) {
        int row = r0 + rg * 8 + r;
        if (col < 64) g_sl[(size_t)row * 64 + col] = acc[r];
        else          g_sr[(size_t)row * 64 + (col - 64)] = acc[r];
    }
}

// ---------------- kernel 2: weight transposes -> fp16 ----------------
__global__ void prep_kernel(const float* __restrict__ W1, const float* __restrict__ W2) {
    int i = blockIdx.x * 256 + threadIdx.x;
    if (i < HID * EMB) {
        {
            int j = i >> 6, d = i & 63;
            g_W1Th[i] = __half_as_ushort(__float2half_rn(W1[d * HID + j]));
        }
        {
            int o = i & 63, jj = i >> 6;
            g_W2Th[o * HID + jj] = __half_as_ushort(__float2half_rn(W2[jj * EMB + o]));
        }
    }
}

// ---------------- kernel 3: positional table ----------------
__global__ void pos_kernel(const float* __restrict__ emb,
                           const float* __restrict__ W1,
                           const float* __restrict__ b1) {
    __shared__ float erow[EMB];
    const int dist = blockIdx.x;
    const int h = threadIdx.x;
    if (h < EMB) erow[h] = emb[dist * EMB + h];
    __syncthreads();
    float acc = b1[h];
#pragma unroll
    for (int d = 0; d < EMB; d++)
        acc = fmaf(erow[d], W1[(EMB + d) * HID + h], acc);
    g_P[dist * HID + h] = acc;
}

// ---------------- main kernel: fp16 2-term, 2 CTAs/SM ----------------
// smem: sl 256B | b2 256B | W1 [128][72] 144B-stride | W2 [64][136] 272B-stride |
//       A'hi [128][72] | A'lo [128][72]
#define OFF_SL   0
#define OFF_B2S  256
#define OFF_W1   512
#define OFF_W2   (OFF_W1 + 18432)
#define OFF_AH   (OFF_W2 + 17408)
#define OFF_AL   (OFF_AH + 18432)
#define SMEM_MAIN (OFF_AL + 18432)   // 73216 bytes -> 2 CTAs/SM

__global__ __launch_bounds__(256, 2)
void pair_mma_kernel(const float* __restrict__ b2, float* __restrict__ out) {
    extern __shared__ char sm[];
    const uint32_t smb = smem_u32_of(sm);
    const int tid = threadIdx.x;
    const int w = tid >> 5, l = tid & 31;
    const int n = blockIdx.x, b = blockIdx.y;

    float* sl = (float*)(sm + OFF_SL);
    float* b2s = (float*)(sm + OFF_B2S);
    if (tid < 64) {
        sl[tid] = g_sl[((size_t)b * N_ + n) * EMB + tid];
        b2s[tid] = b2[tid];
    }

    for (int i = tid; i < 2048; i += 256) {
        int j = i >> 4, d8 = (i & 15) * 8;
        *(uint2*)(sm + OFF_W1 + j * 144 + d8) = ((const uint2*)g_W1Th)[i];
    }
    for (int i = tid; i < 2048; i += 256) {
        int o = i >> 5, j8 = (i & 31) * 8;
        *(uint2*)(sm + OFF_W2 + o * 272 + j8) = ((const uint2*)g_W2Th)[i];
    }

    // ---- per-thread ldmatrix base addresses (all x4 forms) ----
    const uint32_t preA = smb + OFF_AH + (16 * w + (l & 15)) * 144 + (l >> 4) * 16;
    const uint32_t preB1 = smb + OFF_W1 +
        ((l & 7) + ((l >> 4) << 3)) * 144 + ((l >> 3) & 1) * 16;
    const uint32_t preB2 = smb + OFF_W2 +
        ((l & 7) + ((l >> 4) << 3)) * 272 + ((l >> 3) & 1) * 16;

    const int arow = tid >> 1, ac0 = (tid & 1) * 32;
    __syncthreads();

    for (int mt = 0; mt < 4; mt++) {
        // ---- build A'[m][d] = SR[m][d]*sl[d], fp16 hi/lo ----
        {
            const float4* s4 = (const float4*)(g_sr +
                ((size_t)(b * N_ + mt * 128 + arow)) * EMB + ac0);
            const float4* sl4 = (const float4*)(sl + ac0);
            char* dsth = sm + OFF_AH + arow * 144 + ac0 * 2;
            char* dstl = sm + OFF_AL + arow * 144 + ac0 * 2;
#pragma unroll
            for (int i = 0; i < 4; i++) {
                float4 v0 = s4[2 * i], v1 = s4[2 * i + 1];
                float4 w0 = sl4[2 * i], w1 = sl4[2 * i + 1];
                v0.x *= w0.x; v0.y *= w0.y; v0.z *= w0.z; v0.w *= w0.w;
                v1.x *= w1.x; v1.y *= w1.y; v1.z *= w1.z; v1.w *= w1.w;
                uint2 p0 = split2h(v0.x, v0.y), p1 = split2h(v0.z, v0.w);
                uint2 p2 = split2h(v1.x, v1.y), p3 = split2h(v1.z, v1.w);
                *(uint4*)(dsth + i * 16) = make_uint4(p0.x, p1.x, p2.x, p3.x);
                *(uint4*)(dstl + i * 16) = make_uint4(p0.y, p1.y, p2.y, p3.y);
            }
        }
        __syncthreads();

        // ---- GEMM1: H[128,128] = A' @ W1^T, 2-term fp16 ----
        float D1[16][4];
#pragma unroll
        for (int q = 0; q < 16; q++)
#pragma unroll
            for (int e = 0; e < 4; e++) D1[q][e] = 0.0f;

#pragma unroll
        for (int t = 0; t < 4; t++) {
            uint32_t ah[4], al[4];
            ldsm4(ah, preA + t * 32);
            ldsm4(al, preA + 18432 + t * 32);
#pragma unroll
            for (int qq = 0; qq < 8; qq++) {
                uint32_t bh[4];
                ldsm4(bh, preB1 + qq * 2304 + t * 32);
                mma16816(D1[2 * qq],     ah, bh[0], bh[1]);
                mma16816(D1[2 * qq + 1], ah, bh[2], bh[3]);
                mma16816(D1[2 * qq],     al, bh[0], bh[1]);
                mma16816(D1[2 * qq + 1], al, bh[2], bh[3]);
            }
        }
        __syncthreads();   // A' consumed; next tile may rebuild

        // ---- relu(H + P[dist]) in registers ----
        const int m_t = mt * 128 + 16 * w + (l >> 2);
        {
            const float* P0 = g_P + (size_t)(n - m_t + 512) * HID;
            const float* P1 = P0 - 8 * HID;   // row m_t+8
#pragma unroll
            for (int q = 0; q < 16; q++) {
                const int jc = 8 * q + (l & 3) * 2;
                float2 p0 = __ldg((const float2*)(P0 + jc));
                float2 p1 = __ldg((const float2*)(P1 + jc));
                D1[q][0] = fmaxf(D1[q][0] + p0.x, 0.0f);
                D1[q][1] = fmaxf(D1[q][1] + p0.y, 0.0f);
                D1[q][2] = fmaxf(D1[q][2] + p1.x, 0.0f);
                D1[q][3] = fmaxf(D1[q][3] + p1.y, 0.0f);
            }
        }

        // ---- GEMM2: out = Hrelu @ W2, 2-term fp16 (A from registers) ----
        float D2[8][4];
#pragma unroll
        for (int q = 0; q < 8; q++)
#pragma unroll
            for (int e = 0; e < 4; e++) D2[q][e] = 0.0f;

#pragma unroll
        for (int t2 = 0; t2 < 8; t2++) {
            uint32_t ah2[4], al2[4];
            {
                uint2 s0 = split2h(D1[2 * t2][0],     D1[2 * t2][1]);
                uint2 s1 = split2h(D1[2 * t2][2],     D1[2 * t2][3]);
                uint2 s2 = split2h(D1[2 * t2 + 1][0], D1[2 * t2 + 1][1]);
                uint2 s3 = split2h(D1[2 * t2 + 1][2], D1[2 * t2 + 1][3]);
                ah2[0] = s0.x; al2[0] = s0.y;
                ah2[1] = s1.x; al2[1] = s1.y;
                ah2[2] = s2.x; al2[2] = s2.y;
                ah2[3] = s3.x; al2[3] = s3.y;
            }
#pragma unroll
            for (int qq = 0; qq < 4; qq++) {
                uint32_t bh[4];
                ldsm4(bh, preB2 + qq * 4352 + t2 * 32);
                mma16816(D2[2 * qq],     ah2, bh[0], bh[1]);
                mma16816(D2[2 * qq + 1], ah2, bh[2], bh[3]);
                mma16816(D2[2 * qq],     al2, bh[0], bh[1]);
                mma16816(D2[2 * qq + 1], al2, bh[2], bh[3]);
            }
        }

        // ---- epilogue: + b2 (from smem), store fp32 ----
        {
            float* ob = out + (((size_t)b * N_ + n) * N_ + m_t) * EMB;
#pragma unroll
            for (int q = 0; q < 8; q++) {
                const int oc = 8 * q + (l & 3) * 2;
                float2 bb = *(const float2*)(b2s + oc);
                *(float2*)(ob + oc) =
                    make_float2(D2[q][0] + bb.x, D2[q][1] + bb.y);
                *(float2*)(ob + 8 * EMB + oc) =
                    make_float2(D2[q][2] + bb.x, D2[q][3] + bb.y);
            }
        }
    }
}

// ---------------- launch ----------------
extern "C" void kernel_launch(void* const* d_in, const int* in_sizes, int n_in,
                              void* d_out, int out_size) {
    const float* s       = (const float*)d_in[0];
    const float* W_left  = (const float*)d_in[1];
    const float* b_left  = (const float*)d_in[2];
    const float* W_right = (const float*)d_in[3];
    const float* b_right = (const float*)d_in[4];
    const float* emb     = (const float*)d_in[5];
    const float* W1      = (const float*)d_in[6];
    const float* b1      = (const float*)d_in[7];
    const float* W2      = (const float*)d_in[8];
    const float* b2      = (const float*)d_in[9];
    float* out = (float*)d_out;

    cudaFuncSetAttribute(proj2_kernel,
                         cudaFuncAttributeMaxDynamicSharedMemorySize, 73728);
    cudaFuncSetAttribute(pair_mma_kernel,
                         cudaFuncAttributeMaxDynamicSharedMemorySize, SMEM_MAIN);

    proj2_kernel<<<64, 256, 73728>>>(s, W_left, b_left, W_right, b_right);
    prep_kernel<<<32, 256>>>(W1, W2);
    pos_kernel<<<NPOS, 128>>>(emb, W1, b1);
    pair_mma_kernel<<<dim3(N_, B_), 256, SMEM_MAIN>>>(b2, out);
}

// round 10
// speedup vs baseline: 1.5088x; 1.1473x over previous
#include <cuda_runtime.h>
#include <cuda_fp16.h>
#include <stdint.h>

#define B_ 2
#define N_ 512
#define IN_DIM 512
#define EMB 64
#define HID 128
#define NPOS 1025

// ---------------- device scratch (no cudaMalloc allowed) ----------------
__device__ float g_sl[B_ * N_ * EMB];
__device__ float g_sr[B_ * N_ * EMB];
__device__ float g_P[NPOS * HID];
__device__ unsigned short g_W1Th[HID * EMB];   // fp16(W1_top^T) [j][d]
__device__ unsigned short g_W2Th[EMB * HID];   // fp16(W2^T) [o][j]

// ---------------- helpers ----------------
__device__ __forceinline__ uint32_t smem_u32_of(const void* p) {
    uint32_t a;
    asm("{ .reg .u64 t; cvta.to.shared.u64 t, %1; cvt.u32.u64 %0, t; }"
        : "=r"(a) : "l"(p));
    return a;
}
// fp16 hi/lo split of a float pair -> (hi_half2, lo_half2)
__device__ __forceinline__ uint2 split2h(float e0, float e1) {
    __half2 h = __floats2half2_rn(e0, e1);
    float f0 = __half2float(__low2half(h));
    float f1 = __half2float(__high2half(h));
    __half2 lo = __floats2half2_rn(e0 - f0, e1 - f1);
    return make_uint2(*reinterpret_cast<uint32_t*>(&h),
                      *reinterpret_cast<uint32_t*>(&lo));
}
__device__ __forceinline__ void mma16816(float* c, const uint32_t* a,
                                         uint32_t b0, uint32_t b1) {
    asm volatile(
        "mma.sync.aligned.m16n8k16.row.col.f32.f16.f16.f32 "
        "{%0,%1,%2,%3}, {%4,%5,%6,%7}, {%8,%9}, {%0,%1,%2,%3};"
        : "+f"(c[0]), "+f"(c[1]), "+f"(c[2]), "+f"(c[3])
        : "r"(a[0]), "r"(a[1]), "r"(a[2]), "r"(a[3]), "r"(b0), "r"(b1));
}
__device__ __forceinline__ void ldsm4(uint32_t* r, uint32_t addr) {
    asm volatile("ldmatrix.sync.aligned.m8n8.x4.shared.b16 {%0,%1,%2,%3}, [%4];"
                 : "=r"(r[0]), "=r"(r[1]), "=r"(r[2]), "=r"(r[3]) : "r"(addr));
}

// ---------------- kernel 1: projections ----------------
__global__ void proj2_kernel(const float* __restrict__ s,
                             const float* __restrict__ Wl, const float* __restrict__ bl,
                             const float* __restrict__ Wr, const float* __restrict__ br) {
    extern __shared__ float psm[];
    float* SsT = psm;              // [512][20]
    float* Wc  = psm + 512 * 20;   // [64][128]

    const int t = threadIdx.x;
    const int r0 = blockIdx.x * 16;

    for (int i = t; i < 16 * IN_DIM; i += 256) {
        int row = i >> 9, k = i & 511;
        SsT[k * 20 + row] = s[(size_t)(r0 + row) * IN_DIM + k];
    }

    const int col = t & 127, rg = t >> 7;
    float acc[8];
    const float bias = (col < 64) ? bl[col] : br[col - 64];
#pragma unroll
    for (int r = 0; r < 8; r++) acc[r] = bias;
    __syncthreads();

    for (int kt = 0; kt < 8; kt++) {
        for (int i = t; i < 64 * 128; i += 256) {
            int k = i >> 7, c = i & 127;
            Wc[i] = (c < 64) ? Wl[(size_t)(kt * 64 + k) * 64 + c]
                             : Wr[(size_t)(kt * 64 + k) * 64 + (c - 64)];
        }
        __syncthreads();
#pragma unroll 4
        for (int k = 0; k < 64; k++) {
            float w = Wc[k * 128 + col];
            const float* sp = &SsT[(kt * 64 + k) * 20 + rg * 8];
            float4 a0 = *(const float4*)sp;
            float4 a1 = *(const float4*)(sp + 4);
            acc[0] += a0.x * w; acc[1] += a0.y * w; acc[2] += a0.z * w; acc[3] += a0.w * w;
            acc[4] += a1.x * w; acc[5] += a1.y * w; acc[6] += a1.z * w; acc[7] += a1.w * w;
        }
        __syncthreads();
    }
#pragma unroll
    for (int r = 0; r < 8; r++) {
        int row = r0 + rg * 8 + r;
        if (col < 64) g_sl[(size_t)row * 64 + col] = acc[r];
        else          g_sr[(size_t)row * 64 + (col - 64)] = acc[r];
    }
}

// ---------------- kernel 2: weight transposes -> fp16 ----------------
__global__ void prep_kernel(const float* __restrict__ W1, const float* __restrict__ W2) {
    int i = blockIdx.x * 256 + threadIdx.x;
    if (i < HID * EMB) {
        {
            int j = i >> 6, d = i & 63;
            g_W1Th[i] = __half_as_ushort(__float2half_rn(W1[d * HID + j]));
        }
        {
            int o = i & 63, jj = i >> 6;
            g_W2Th[o * HID + jj] = __half_as_ushort(__float2half_rn(W2[jj * EMB + o]));
        }
    }
}

// ---------------- kernel 3: positional table ----------------
__global__ void pos_kernel(const float* __restrict__ emb,
                           const float* __restrict__ W1,
                           const float* __restrict__ b1) {
    __shared__ float erow[EMB];
    const int dist = blockIdx.x;
    const int h = threadIdx.x;
    if (h < EMB) erow[h] = emb[dist * EMB + h];
    __syncthreads();
    float acc = b1[h];
#pragma unroll
    for (int d = 0; d < EMB; d++)
        acc = fmaf(erow[d], W1[(EMB + d) * HID + h], acc);
    g_P[dist * HID + h] = acc;
}

// ---------------- main kernel: register-built A fragments, barrier-free loop ----------------
// smem: sl 256B | b2 256B | W1 [128 j][72 fp16] 144B-stride | W2 [64 o][136] 272B-stride
#define OFF_SL   0
#define OFF_B2S  256
#define OFF_W1   512
#define OFF_W2   (OFF_W1 + 18432)
#define SMEM_MAIN (OFF_W2 + 17408)   // 36352 bytes

__global__ __launch_bounds__(256, 2)
void pair_mma_kernel(const float* __restrict__ b2, float* __restrict__ out) {
    extern __shared__ char sm[];
    const uint32_t smb = smem_u32_of(sm);
    const int tid = threadIdx.x;
    const int w = tid >> 5, l = tid & 31;
    const int n = blockIdx.x, b = blockIdx.y;

    float* sl = (float*)(sm + OFF_SL);
    float* b2s = (float*)(sm + OFF_B2S);
    if (tid < 64) {
        sl[tid] = g_sl[((size_t)b * N_ + n) * EMB + tid];
        b2s[tid] = b2[tid];
    }

    for (int i = tid; i < 2048; i += 256) {
        int j = i >> 4, d8 = (i & 15) * 8;
        *(uint2*)(sm + OFF_W1 + j * 144 + d8) = ((const uint2*)g_W1Th)[i];
    }
    for (int i = tid; i < 2048; i += 256) {
        int o = i >> 5, j8 = (i & 31) * 8;
        *(uint2*)(sm + OFF_W2 + o * 272 + j8) = ((const uint2*)g_W2Th)[i];
    }

    // ---- per-thread ldmatrix base addresses for B operands (x4 forms) ----
    const uint32_t preB1 = smb + OFF_W1 +
        ((l & 7) + ((l >> 4) << 3)) * 144 + ((l >> 3) & 1) * 16;
    const uint32_t preB2 = smb + OFF_W2 +
        ((l & 7) + ((l >> 4) << 3)) * 272 + ((l >> 3) & 1) * 16;

    // ---- A-fragment geometry: rows fr0, fr0+8; cols (l&3)*2 + {0,8} + 16t ----
    const int fr0 = 16 * w + (l >> 2);
    const int fc0 = (l & 3) * 2;

    __syncthreads();   // smem now read-only: the mt loop below has NO barriers

    for (int mt = 0; mt < 4; mt++) {
        const int m_t = mt * 128 + fr0;

        // ---- build GEMM1 A fragments directly in registers (no smem staging) ----
        uint32_t ah[4][4], al[4][4];
        {
            const float* sr0 = g_sr + ((size_t)(b * N_ + mt * 128 + fr0)) * EMB;
            const float* sr8 = sr0 + 8 * EMB;
#pragma unroll
            for (int t = 0; t < 4; t++) {
                const int c = fc0 + 16 * t;
                float2 v00 = *(const float2*)(sr0 + c);
                float2 v01 = *(const float2*)(sr0 + c + 8);
                float2 v10 = *(const float2*)(sr8 + c);
                float2 v11 = *(const float2*)(sr8 + c + 8);
                float2 s0 = *(const float2*)(sl + c);
                float2 s1 = *(const float2*)(sl + c + 8);
                uint2 p0 = split2h(v00.x * s0.x, v00.y * s0.y);  // a0: row, c
                uint2 p1 = split2h(v10.x * s0.x, v10.y * s0.y);  // a1: row+8, c
                uint2 p2 = split2h(v01.x * s1.x, v01.y * s1.y);  // a2: row, c+8
                uint2 p3 = split2h(v11.x * s1.x, v11.y * s1.y);  // a3: row+8, c+8
                ah[t][0] = p0.x; al[t][0] = p0.y;
                ah[t][1] = p1.x; al[t][1] = p1.y;
                ah[t][2] = p2.x; al[t][2] = p2.y;
                ah[t][3] = p3.x; al[t][3] = p3.y;
            }
        }

        // ---- GEMM1: H[16,128] per warp = A' @ W1^T, 2-term fp16 ----
        float D1[16][4];
#pragma unroll
        for (int q = 0; q < 16; q++)
#pragma unroll
            for (int e = 0; e < 4; e++) D1[q][e] = 0.0f;

#pragma unroll
        for (int t = 0; t < 4; t++) {
#pragma unroll
            for (int qq = 0; qq < 8; qq++) {
                uint32_t bh[4];
                ldsm4(bh, preB1 + qq * 2304 + t * 32);
                mma16816(D1[2 * qq],     ah[t], bh[0], bh[1]);
                mma16816(D1[2 * qq + 1], ah[t], bh[2], bh[3]);
                mma16816(D1[2 * qq],     al[t], bh[0], bh[1]);
                mma16816(D1[2 * qq + 1], al[t], bh[2], bh[3]);
            }
        }

        // ---- relu(H + P[dist]) in registers ----
        {
            const float* P0 = g_P + (size_t)(n - m_t + 512) * HID;
            const float* P1 = P0 - 8 * HID;   // row m_t+8
#pragma unroll
            for (int q = 0; q < 16; q++) {
                const int jc = 8 * q + fc0;
                float2 p0 = __ldg((const float2*)(P0 + jc));
                float2 p1 = __ldg((const float2*)(P1 + jc));
                D1[q][0] = fmaxf(D1[q][0] + p0.x, 0.0f);
                D1[q][1] = fmaxf(D1[q][1] + p0.y, 0.0f);
                D1[q][2] = fmaxf(D1[q][2] + p1.x, 0.0f);
                D1[q][3] = fmaxf(D1[q][3] + p1.y, 0.0f);
            }
        }

        // ---- GEMM2: out = Hrelu @ W2, 2-term fp16 (A from registers) ----
        float D2[8][4];
#pragma unroll
        for (int q = 0; q < 8; q++)
#pragma unroll
            for (int e = 0; e < 4; e++) D2[q][e] = 0.0f;

#pragma unroll
        for (int t2 = 0; t2 < 8; t2++) {
            uint32_t ah2[4], al2[4];
            {
                uint2 s0 = split2h(D1[2 * t2][0],     D1[2 * t2][1]);
                uint2 s1 = split2h(D1[2 * t2][2],     D1[2 * t2][3]);
                uint2 s2 = split2h(D1[2 * t2 + 1][0], D1[2 * t2 + 1][1]);
                uint2 s3 = split2h(D1[2 * t2 + 1][2], D1[2 * t2 + 1][3]);
                ah2[0] = s0.x; al2[0] = s0.y;
                ah2[1] = s1.x; al2[1] = s1.y;
                ah2[2] = s2.x; al2[2] = s2.y;
                ah2[3] = s3.x; al2[3] = s3.y;
            }
#pragma unroll
            for (int qq = 0; qq < 4; qq++) {
                uint32_t bh[4];
                ldsm4(bh, preB2 + qq * 4352 + t2 * 32);
                mma16816(D2[2 * qq],     ah2, bh[0], bh[1]);
                mma16816(D2[2 * qq + 1], ah2, bh[2], bh[3]);
                mma16816(D2[2 * qq],     al2, bh[0], bh[1]);
                mma16816(D2[2 * qq + 1], al2, bh[2], bh[3]);
            }
        }

        // ---- epilogue: + b2 (from smem), store fp32 ----
        {
            float* ob = out + (((size_t)b * N_ + n) * N_ + m_t) * EMB;
#pragma unroll
            for (int q = 0; q < 8; q++) {
                const int oc = 8 * q + fc0;
                float2 bb = *(const float2*)(b2s + oc);
                *(float2*)(ob + oc) =
                    make_float2(D2[q][0] + bb.x, D2[q][1] + bb.y);
                *(float2*)(ob + 8 * EMB + oc) =
                    make_float2(D2[q][2] + bb.x, D2[q][3] + bb.y);
            }
        }
    }
}

// ---------------- launch ----------------
extern "C" void kernel_launch(void* const* d_in, const int* in_sizes, int n_in,
                              void* d_out, int out_size) {
    const float* s       = (const float*)d_in[0];
    const float* W_left  = (const float*)d_in[1];
    const float* b_left  = (const float*)d_in[2];
    const float* W_right = (const float*)d_in[3];
    const float* b_right = (const float*)d_in[4];
    const float* emb     = (const float*)d_in[5];
    const float* W1      = (const float*)d_in[6];
    const float* b1      = (const float*)d_in[7];
    const float* W2      = (const float*)d_in[8];
    const float* b2      = (const float*)d_in[9];
    float* out = (float*)d_out;

    cudaFuncSetAttribute(proj2_kernel,
                         cudaFuncAttributeMaxDynamicSharedMemorySize, 73728);
    cudaFuncSetAttribute(pair_mma_kernel,
                         cudaFuncAttributeMaxDynamicSharedMemorySize, SMEM_MAIN);

    proj2_kernel<<<64, 256, 73728>>>(s, W_left, b_left, W_right, b_right);
    prep_kernel<<<32, 256>>>(W1, W2);
    pos_kernel<<<NPOS, 128>>>(emb, W1, b1);
    pair_mma_kernel<<<dim3(N_, B_), 256, SMEM_MAIN>>>(b2, out);
}